// round 2
// baseline (speedup 1.0000x reference)
#include <cuda_runtime.h>
#include <cuda_bf16.h>

#define IN_F   4096
#define OUT_F  11008
#define GRP    128
#define MROWS  32
#define NGRP   (IN_F / GRP)          // 32 groups
#define KSPLIT 16
#define GROUPS_PER_CTA (NGRP / KSPLIT)   // 2
#define THREADS 128
#define COLS_PER_CTA 256             // 4 warps * 32 lanes * 2 cols
#define CTAS_COL (OUT_F / COLS_PER_CTA)  // 43
#define PAD 36                       // floats per xs row: 144B = 9 x 16B -> conflict-free STS.128

// K-split partial sums (scratch; no alloc allowed in kernel_launch)
__device__ float g_partial[(size_t)KSPLIT * MROWS * OUT_F];

__device__ __forceinline__ float bfr(float v) {
    return __bfloat162float(__float2bfloat16(v));
}

// ---------------------------------------------------------------------------
// Main GEMM: lane owns 2 adjacent output columns x all 32 rows.
// Per k: 1 LDG.64 weights, dequant x2, 8 broadcast LDS.128 -> 32 FFMA2.
// ---------------------------------------------------------------------------
__global__ void __launch_bounds__(THREADS)
qlinear_main(const float* __restrict__ x,
             const int*   __restrict__ qweight,
             const int*   __restrict__ qzeros,
             const float* __restrict__ scales)
{
    __shared__ __align__(16) float xs[GRP * PAD];

    const int bx    = blockIdx.x;
    const int ctile = bx % CTAS_COL;
    const int kq    = bx / CTAS_COL;
    const int tid   = threadIdx.x;
    const int warp  = tid >> 5;
    const int lane  = tid & 31;
    const int o0    = ctile * COLS_PER_CTA + warp * 64 + lane * 2;

    // acc[c][r] packs rows (2r, 2r+1) for column o0+c
    unsigned long long acc[2][16];
    #pragma unroll
    for (int c = 0; c < 2; c++)
        #pragma unroll
        for (int r = 0; r < 16; r++) acc[c][r] = 0ULL;

    const int g0 = kq * GROUPS_PER_CTA;

    for (int gg = 0; gg < GROUPS_PER_CTA; gg++) {
        const int g     = g0 + gg;
        const int ibase = g * GRP;

        __syncthreads();   // previous group's xs reads complete
        // ---- stage x chunk: xs[k][s], bf16-rounded, conflict-free STS.128 ----
        #pragma unroll
        for (int r = 0; r < 8; r++) {
            const int s = 4 * r;
            float4 f4;
            f4.x = bfr(x[(size_t)(s + 0) * IN_F + ibase + tid]);
            f4.y = bfr(x[(size_t)(s + 1) * IN_F + ibase + tid]);
            f4.z = bfr(x[(size_t)(s + 2) * IN_F + ibase + tid]);
            f4.w = bfr(x[(size_t)(s + 3) * IN_F + ibase + tid]);
            *(float4*)(xs + (size_t)tid * PAD + s) = f4;
        }
        __syncthreads();

        // per-(group, column-pair) dequant constants
        const float2 scv = *(const float2*)(scales + (size_t)g * OUT_F + o0);
        const int2   qzv = *(const int2*)  (qzeros + (size_t)g * OUT_F + o0);
        const float sc0 = bfr(scv.x);
        const float sc1 = bfr(scv.y);
        const float mq0 = -(float)qzv.x * sc0;
        const float mq1 = -(float)qzv.y * sc1;

        const int2* wp = (const int2*)(qweight + (size_t)ibase * OUT_F) + (o0 >> 1);

        #pragma unroll 1
        for (int i = 0; i < GRP; i += 4) {
            // batch 4 weight row loads for MLP
            int2 w0 = wp[0 * (OUT_F / 2)];
            int2 w1 = wp[1 * (OUT_F / 2)];
            int2 w2 = wp[2 * (OUT_F / 2)];
            int2 w3 = wp[3 * (OUT_F / 2)];
            wp += 4 * (OUT_F / 2);

            #pragma unroll
            for (int u = 0; u < 4; u++) {
                int2 w = (u == 0) ? w0 : (u == 1) ? w1 : (u == 2) ? w2 : w3;
                float wa = fmaf((float)w.x, sc0, mq0);   // (qw - qz) * sc, exact
                float wb = fmaf((float)w.y, sc1, mq1);
                unsigned long long pa, pb;
                asm("mov.b64 %0, {%1, %1};" : "=l"(pa) : "f"(wa));
                asm("mov.b64 %0, {%1, %1};" : "=l"(pb) : "f"(wb));

                const ulonglong2* xr =
                    (const ulonglong2*)(xs + (size_t)(i + u) * PAD);
                #pragma unroll
                for (int q = 0; q < 8; q++) {
                    ulonglong2 xv = xr[q];   // broadcast LDS.128: rows 4q..4q+3
                    asm("fma.rn.f32x2 %0, %1, %2, %0;"
                        : "+l"(acc[0][2 * q])     : "l"(pa), "l"(xv.x));
                    asm("fma.rn.f32x2 %0, %1, %2, %0;"
                        : "+l"(acc[0][2 * q + 1]) : "l"(pa), "l"(xv.y));
                    asm("fma.rn.f32x2 %0, %1, %2, %0;"
                        : "+l"(acc[1][2 * q])     : "l"(pb), "l"(xv.x));
                    asm("fma.rn.f32x2 %0, %1, %2, %0;"
                        : "+l"(acc[1][2 * q + 1]) : "l"(pb), "l"(xv.y));
                }
            }
        }
    }

    // ---- write K-split partials (coalesced STG.64, no atomics) ----
    float* pp = g_partial + ((size_t)kq * MROWS) * OUT_F + o0;
    #pragma unroll
    for (int r = 0; r < 16; r++) {
        float a0, a1, b0, b1;
        asm("mov.b64 {%0, %1}, %2;" : "=f"(a0), "=f"(a1) : "l"(acc[0][r]));
        asm("mov.b64 {%0, %1}, %2;" : "=f"(b0), "=f"(b1) : "l"(acc[1][r]));
        float2 lo = make_float2(a0, b0);   // row 2r,   cols (o0, o0+1)
        float2 hi = make_float2(a1, b1);   // row 2r+1
        *(float2*)(pp + (size_t)(2 * r)     * OUT_F) = lo;
        *(float2*)(pp + (size_t)(2 * r + 1) * OUT_F) = hi;
    }
}

// ---------------------------------------------------------------------------
// Epilogue: out[s][o] = bf16(bias[o]) + sum_p partial[p][s][o]
// ---------------------------------------------------------------------------
__global__ void __launch_bounds__(256)
reduce_kernel(const float* __restrict__ bias, float* __restrict__ out)
{
    const int o = blockIdx.x * 256 + threadIdx.x;
    const int s = blockIdx.y;
    if (o < OUT_F) {
        float a = bfr(bias[o]);
        #pragma unroll
        for (int p = 0; p < KSPLIT; p++)
            a += g_partial[((size_t)p * MROWS + s) * OUT_F + o];
        out[(size_t)s * OUT_F + o] = a;
    }
}

// ---------------------------------------------------------------------------
// inputs: x f32[1,32,4096], qweight i32[4096,11008], qzeros i32[32,11008],
//         scales f32[32,11008], bias f32[11008]; output f32[1,32,11008]
// ---------------------------------------------------------------------------
extern "C" void kernel_launch(void* const* d_in, const int* in_sizes, int n_in,
                              void* d_out, int out_size)
{
    const float* x       = (const float*)d_in[0];
    const int*   qweight = (const int*)  d_in[1];
    const int*   qzeros  = (const int*)  d_in[2];
    const float* scales  = (const float*)d_in[3];
    const float* bias    = (const float*)d_in[4];
    float*       out     = (float*)d_out;

    qlinear_main<<<CTAS_COL * KSPLIT, THREADS>>>(x, qweight, qzeros, scales);
    reduce_kernel<<<dim3(CTAS_COL, MROWS), 256>>>(bias, out);
}

// round 5
// speedup vs baseline: 3.4668x; 3.4668x over previous
#include <cuda_runtime.h>
#include <cuda_bf16.h>
#include <cstdint>

#define IN_F     4096
#define OUT_F    11008
#define MROWS    32
#define GRP      128
#define KSPLIT   2
#define KPER     (IN_F / KSPLIT)          // 2048
#define NGROUPS  (KPER / GRP)             // 16
#define NTILE    64
#define CTAS_COL (OUT_F / NTILE)          // 172
#define THREADS  128

#define XROW_B   272                      // x row: 256B data + 16B pad (odd 16B count -> ldmatrix conflict-free)
#define WROW_W   67                       // w row: 64 words (128 bf16) + 3 pad words
#define WROW_B   (WROW_W * 4)             // 268B

__device__ __forceinline__ float bfr(float v) {
    return __bfloat162float(__float2bfloat16(v));
}

__device__ __forceinline__ uint32_t pack_bf16x2(float hi, float lo) {
    uint32_t r;
    asm("cvt.rn.bf16x2.f32 %0, %1, %2;" : "=r"(r) : "f"(hi), "f"(lo));
    return r;
}

__device__ __forceinline__ void hmma(float c[4], const uint32_t a[4],
                                     uint32_t b0, uint32_t b1) {
    asm volatile(
        "mma.sync.aligned.m16n8k16.row.col.f32.bf16.bf16.f32 "
        "{%0,%1,%2,%3}, {%4,%5,%6,%7}, {%8,%9}, {%0,%1,%2,%3};"
        : "+f"(c[0]), "+f"(c[1]), "+f"(c[2]), "+f"(c[3])
        : "r"(a[0]), "r"(a[1]), "r"(a[2]), "r"(a[3]), "r"(b0), "r"(b1));
}

// ---------------------------------------------------------------------------
__global__ void init_out_kernel(const float* __restrict__ bias,
                                float* __restrict__ out)
{
    int o = blockIdx.x * blockDim.x + threadIdx.x;
    if (o < OUT_F) {
        float b = bfr(bias[o]);
        #pragma unroll
        for (int s = 0; s < MROWS; s++)
            out[(size_t)s * OUT_F + o] = b;
    }
}

// ---------------------------------------------------------------------------
// Per CTA: 64 output cols x 2048 K; warp w owns local cols [16w, 16w+16).
// Per group(128 K): stage bf16(x) [32x128] + bf16(qw-qz) [64n x 128k] in SMEM,
// 8 mma.sync k-steps; per-group scale applied in register epilogue
// (exact: (qw-qz) is a 5-bit integer, bf16-exact; scale distributes).
// ---------------------------------------------------------------------------
__global__ void __launch_bounds__(THREADS, 1)
qmain(const float* __restrict__ x, const int* __restrict__ qweight,
      const int* __restrict__ qzeros, const float* __restrict__ scales,
      float* __restrict__ out)
{
    __shared__ __align__(16) uint8_t xs_raw[MROWS * XROW_B];   //  8704 B
    __shared__ __align__(16) uint8_t ws_raw[NTILE * WROW_B];   // 17152 B

    uint32_t xs_b, ws_b;
    asm("{ .reg .u64 t; cvta.to.shared.u64 t, %1; cvt.u32.u64 %0, t; }"
        : "=r"(xs_b) : "l"(xs_raw));
    asm("{ .reg .u64 t; cvta.to.shared.u64 t, %1; cvt.u32.u64 %0, t; }"
        : "=r"(ws_b) : "l"(ws_raw));

    const int tid   = threadIdx.x;
    const int w     = tid >> 5;
    const int l     = tid & 31;
    const int bx    = blockIdx.x;
    const int ctile = bx % CTAS_COL;
    const int kq    = bx / CTAS_COL;
    const int o0    = ctile * NTILE;

    // conversion mapping
    const int khalf = l >> 4;              // 0/1
    const int oq    = l & 15;              // o-quad index
    const int ocol  = 4 * oq;              // local col 0..60

    // ldmatrix A lane address: row = l&15, k-chunk(8) = l>>4
    const uint32_t a_lane_off = (uint32_t)(l & 15) * XROW_B + (uint32_t)(l >> 4) * 16;

    const int gid = l >> 2;                // C/B fragment group id
    const int tig = l & 3;                 // thread-in-group

    // total accumulators: [m-frag][n-subtile][reg]
    float ct[2][2][4];
    #pragma unroll
    for (int mi = 0; mi < 2; mi++)
        #pragma unroll
        for (int t = 0; t < 2; t++)
            #pragma unroll
            for (int r = 0; r < 4; r++) ct[mi][t][r] = 0.0f;

    for (int g = 0; g < NGROUPS; g++) {
        const int kb = kq * KPER + g * GRP;   // global k base of this group
        const int gg = kb >> 7;               // global group index

        __syncthreads();   // prior group's SMEM reads complete

        // ---- stage x[0:32][kb:kb+128] -> bf16, STS.64 ----
        #pragma unroll
        for (int j = 0; j < 8; j++) {
            int idx = tid + THREADS * j;      // 0..1023
            int s   = idx >> 5;               // row 0..31
            int kq4 = idx & 31;               // float4 index in row
            float4 v = *(const float4*)(x + (size_t)s * IN_F + kb + 4 * kq4);
            uint32_t p0 = pack_bf16x2(v.y, v.x);
            uint32_t p1 = pack_bf16x2(v.w, v.z);
            uint32_t a = xs_b + (uint32_t)s * XROW_B + (uint32_t)kq4 * 8;
            asm volatile("st.shared.v2.b32 [%0], {%1,%2};" :: "r"(a), "r"(p0), "r"(p1));
        }

        // ---- stage W: (qw - qz) -> bf16, transposed to [n][k] ----
        {
            int4 qz = *(const int4*)(qzeros + (size_t)gg * OUT_F + o0 + ocol);
            #pragma unroll
            for (int it = 0; it < 8; it++) {
                int kblk = w * 32 + it * 4 + 2 * khalf;       // even
                const int* p = qweight + (size_t)(kb + kblk) * OUT_F + o0 + ocol;
                int4 w0 = *(const int4*)p;
                int4 w1 = *(const int4*)(p + OUT_F);
                uint32_t r0 = pack_bf16x2((float)(w1.x - qz.x), (float)(w0.x - qz.x));
                uint32_t r1 = pack_bf16x2((float)(w1.y - qz.y), (float)(w0.y - qz.y));
                uint32_t r2 = pack_bf16x2((float)(w1.z - qz.z), (float)(w0.z - qz.z));
                uint32_t r3 = pack_bf16x2((float)(w1.w - qz.w), (float)(w0.w - qz.w));
                uint32_t a = ws_b + (uint32_t)ocol * WROW_B + (uint32_t)(kblk >> 1) * 4;
                asm volatile("st.shared.b32 [%0], %1;" :: "r"(a), "r"(r0));
                asm volatile("st.shared.b32 [%0], %1;" :: "r"(a + WROW_B), "r"(r1));
                asm volatile("st.shared.b32 [%0], %1;" :: "r"(a + 2 * WROW_B), "r"(r2));
                asm volatile("st.shared.b32 [%0], %1;" :: "r"(a + 3 * WROW_B), "r"(r3));
            }
        }

        __syncthreads();

        // ---- 8 k16-steps of mma.sync into per-group accumulators ----
        float cg[2][2][4];
        #pragma unroll
        for (int mi = 0; mi < 2; mi++)
            #pragma unroll
            for (int t = 0; t < 2; t++)
                #pragma unroll
                for (int r = 0; r < 4; r++) cg[mi][t][r] = 0.0f;

        #pragma unroll
        for (int ks = 0; ks < 8; ks++) {
            uint32_t a0[4], a1[4];
            uint32_t addr0 = xs_b + a_lane_off + (uint32_t)ks * 32;
            uint32_t addr1 = addr0 + 16u * XROW_B;
            asm volatile("ldmatrix.sync.aligned.m8n8.x4.shared.b16 {%0,%1,%2,%3}, [%4];"
                         : "=r"(a0[0]), "=r"(a0[1]), "=r"(a0[2]), "=r"(a0[3]) : "r"(addr0));
            asm volatile("ldmatrix.sync.aligned.m8n8.x4.shared.b16 {%0,%1,%2,%3}, [%4];"
                         : "=r"(a1[0]), "=r"(a1[1]), "=r"(a1[2]), "=r"(a1[3]) : "r"(addr1));

            #pragma unroll
            for (int t = 0; t < 2; t++) {
                uint32_t n = (uint32_t)(w * 16 + t * 8 + gid);   // warp-partitioned N
                uint32_t baddr = ws_b + n * WROW_B + (uint32_t)(ks * 8 + tig) * 4;
                uint32_t b0, b1;
                asm volatile("ld.shared.b32 %0, [%1];" : "=r"(b0) : "r"(baddr));
                asm volatile("ld.shared.b32 %0, [%1];" : "=r"(b1) : "r"(baddr + 16));
                hmma(cg[0][t], a0, b0, b1);
                hmma(cg[1][t], a1, b0, b1);
            }
        }

        // ---- per-group scale epilogue (registers only) ----
        #pragma unroll
        for (int t = 0; t < 2; t++) {
            float2 scv = *(const float2*)(scales + (size_t)gg * OUT_F
                                          + o0 + w * 16 + t * 8 + 2 * tig);
            float s0 = bfr(scv.x);
            float s1 = bfr(scv.y);
            #pragma unroll
            for (int mi = 0; mi < 2; mi++) {
                ct[mi][t][0] = fmaf(cg[mi][t][0], s0, ct[mi][t][0]);
                ct[mi][t][1] = fmaf(cg[mi][t][1], s1, ct[mi][t][1]);
                ct[mi][t][2] = fmaf(cg[mi][t][2], s0, ct[mi][t][2]);
                ct[mi][t][3] = fmaf(cg[mi][t][3], s1, ct[mi][t][3]);
            }
        }
    }

    // ---- K-split reduction into bias-initialized output ----
    #pragma unroll
    for (int mi = 0; mi < 2; mi++) {
        int s0 = mi * 16 + gid;
        #pragma unroll
        for (int t = 0; t < 2; t++) {
            int oc = o0 + w * 16 + t * 8 + 2 * tig;
            atomicAdd(&out[(size_t)s0 * OUT_F + oc],           ct[mi][t][0]);
            atomicAdd(&out[(size_t)s0 * OUT_F + oc + 1],       ct[mi][t][1]);
            atomicAdd(&out[(size_t)(s0 + 8) * OUT_F + oc],     ct[mi][t][2]);
            atomicAdd(&out[(size_t)(s0 + 8) * OUT_F + oc + 1], ct[mi][t][3]);
        }
    }
}

// ---------------------------------------------------------------------------
// inputs: x f32[1,32,4096], qweight i32[4096,11008], qzeros i32[32,11008],
//         scales f32[32,11008], bias f32[11008]; output f32[1,32,11008]
// ---------------------------------------------------------------------------
extern "C" void kernel_launch(void* const* d_in, const int* in_sizes, int n_in,
                              void* d_out, int out_size)
{
    const float* x       = (const float*)d_in[0];
    const int*   qweight = (const int*)  d_in[1];
    const int*   qzeros  = (const int*)  d_in[2];
    const float* scales  = (const float*)d_in[3];
    const float* bias    = (const float*)d_in[4];
    float*       out     = (float*)d_out;

    init_out_kernel<<<(OUT_F + 255) / 256, 256>>>(bias, out);
    qmain<<<CTAS_COL * KSPLIT, THREADS>>>(x, qweight, qzeros, scales, out);
}